// round 5
// baseline (speedup 1.0000x reference)
#include <cuda_runtime.h>
#include <math.h>
#include <stdint.h>

// Problem constants
#define T      4096
#define DH     64
#define NH     4        // n_hashes
#define NB     64       // buckets per hash
#define DM     512
#define BHN    32       // B*H
#define SELF_VAL (-5e4f)

// ---------------- scratch (device globals; no allocation allowed) ----------------
__device__ float g_qk [(size_t)BHN * T * DH];        // merged qk  (bh, t, dh)
__device__ float g_v  [(size_t)BHN * T * DH];        // merged v
__device__ int   g_st [BHN * NH * T];                // sorted original positions
__device__ float g_o  [(size_t)BHN * NH * T * DH];   // per-round outputs
__device__ float g_lse[BHN * NH * T];                // per-round logsumexp
__device__ float g_ctx[(size_t)4 * T * DM];          // combined context (B,T,DM)

extern __shared__ float smem[];

// ---------------- fp32 GEMM (W_qk only: feeds hash argmax, must stay exact) ----------
__global__ __launch_bounds__(256)
void gemm_qk_kernel(const float* __restrict__ A,
                    const float* __restrict__ Bm)
{
    const int N = 512, K = 512;
    __shared__ float As[2][16][132];   // [k][m]
    __shared__ float Bs[2][16][68];    // [k][n]

    int tid = threadIdx.x;
    int tx = tid & 15, ty = tid >> 4;
    int bm = blockIdx.y * 128, bn = blockIdx.x * 64;

    int f0 = tid * 2, f1 = tid * 2 + 1;
    int a_row0 = f0 >> 2, a_k0 = (f0 & 3) << 2;
    int a_row1 = f1 >> 2, a_k1 = (f1 & 3) << 2;
    int b_k = tid >> 4, b_n = (tid & 15) << 2;

    float4 ar0, ar1, br;
    float acc[8][4] = {};

#define LDG_TILE(k0)                                                              \
    {   ar0 = *(const float4*)&A[(size_t)(bm + a_row0) * K + (k0) + a_k0];        \
        ar1 = *(const float4*)&A[(size_t)(bm + a_row1) * K + (k0) + a_k1];        \
        br  = *(const float4*)&Bm[(size_t)((k0) + b_k) * N + bn + b_n]; }
#define STS_TILE(buf)                                                             \
    {   As[buf][a_k0 + 0][a_row0] = ar0.x; As[buf][a_k0 + 1][a_row0] = ar0.y;     \
        As[buf][a_k0 + 2][a_row0] = ar0.z; As[buf][a_k0 + 3][a_row0] = ar0.w;     \
        As[buf][a_k1 + 0][a_row1] = ar1.x; As[buf][a_k1 + 1][a_row1] = ar1.y;     \
        As[buf][a_k1 + 2][a_row1] = ar1.z; As[buf][a_k1 + 3][a_row1] = ar1.w;     \
        *(float4*)&Bs[buf][b_k][b_n] = br; }

    LDG_TILE(0); STS_TILE(0); __syncthreads();

    const int NST = K / 16;   // 32
    for (int s = 0; s < NST; s++) {
        if (s + 1 < NST) LDG_TILE((s + 1) * 16);
        int buf = s & 1;
        #pragma unroll
        for (int k = 0; k < 16; k++) {
            float4 a0 = *(const float4*)&As[buf][k][ty * 8];
            float4 a1 = *(const float4*)&As[buf][k][ty * 8 + 4];
            float4 b4 = *(const float4*)&Bs[buf][k][tx * 4];
            float a[8] = {a0.x, a0.y, a0.z, a0.w, a1.x, a1.y, a1.z, a1.w};
            float b[4] = {b4.x, b4.y, b4.z, b4.w};
            #pragma unroll
            for (int i = 0; i < 8; i++)
                #pragma unroll
                for (int j = 0; j < 4; j++)
                    acc[i][j] = fmaf(a[i], b[j], acc[i][j]);
        }
        if (s + 1 < NST) STS_TILE((s + 1) & 1);
        __syncthreads();
    }

    #pragma unroll
    for (int i = 0; i < 8; i++) {
        int m = bm + ty * 8 + i;
        #pragma unroll
        for (int j = 0; j < 4; j++) {
            int n = bn + tx * 4 + j;
            int b = m >> 12, t = m & 4095;
            int h = n >> 6,  d = n & 63;
            g_qk[(((size_t)(b * 8 + h)) * T + t) * DH + d] = acc[i][j];
        }
    }
#undef LDG_TILE
#undef STS_TILE
}

// ---------------- 3xTF32 tensor-core GEMM (W_v merged / W_out + bias) -------------
// 128x128 block tile, 8 warps (4x2), 32x64 warp tile, mma.m16n8k8.tf32, hi/lo split.
__device__ __forceinline__ uint32_t f2tf32(float x) {
    uint32_t u; asm("cvt.rna.tf32.f32 %0, %1;" : "=r"(u) : "f"(x)); return u;
}

#define MMA_TF32(c, a, b)                                                          \
    asm volatile("mma.sync.aligned.m16n8k8.row.col.f32.tf32.tf32.f32 "             \
                 "{%0,%1,%2,%3},{%4,%5,%6,%7},{%8,%9},{%0,%1,%2,%3};"              \
                 : "+f"(c[0]), "+f"(c[1]), "+f"(c[2]), "+f"(c[3])                  \
                 : "r"(a[0]), "r"(a[1]), "r"(a[2]), "r"(a[3]), "r"(b[0]), "r"(b[1]))

#define TCP 136                       // smem pitch (conflict-free: banks t*8+g)
#define TC_STAGE (4 * 16 * TCP)       // Ahi,Alo,Bhi,Blo each [16][TCP]
#define SMEM_TC (2 * TC_STAGE * 4)    // 69632 B

// MODE 1: write g_v merged; MODE 2: C = acc + bias
template <int MODE>
__global__ __launch_bounds__(256)
void gemm_tc_kernel(const float* __restrict__ A,
                    const float* __restrict__ Bm,
                    const float* __restrict__ bias,
                    float* __restrict__ C)
{
    const int K = 512, N = 512;
    const float* Ap = (MODE == 2) ? g_ctx : A;

    int tid = threadIdx.x, lane = tid & 31, wid = tid >> 5;
    int wm = wid >> 1, wn = wid & 1;
    int m0w = wm * 32, n0w = wn * 64;
    int g = lane >> 2, t = lane & 3;
    int bm = blockIdx.y * 128, bn = blockIdx.x * 128;

    // global-load mapping
    int ar = tid >> 1, ak = (tid & 1) * 8;          // A[ar][ak..ak+7]
    int bk = tid >> 5, bn4 = (tid & 31) * 4;        // B[bk(+8)][bn4..bn4+3]

    uint32_t* smu = (uint32_t*)smem;
    float4 a4_0, a4_1, b4_0, b4_1;
    float acc[2][8][4] = {};

#define TC_LDG(k0)                                                                   \
    {   a4_0 = *(const float4*)&Ap[(size_t)(bm + ar) * K + (k0) + ak];               \
        a4_1 = *(const float4*)&Ap[(size_t)(bm + ar) * K + (k0) + ak + 4];           \
        b4_0 = *(const float4*)&Bm[(size_t)((k0) + bk) * N + bn + bn4];              \
        b4_1 = *(const float4*)&Bm[(size_t)((k0) + bk + 8) * N + bn + bn4]; }

#define TC_STS(s)                                                                    \
    {   uint32_t* sAhi = smu + (s) * TC_STAGE;                                       \
        uint32_t* sAlo = sAhi + 16 * TCP;                                            \
        uint32_t* sBhi = sAlo + 16 * TCP;                                            \
        uint32_t* sBlo = sBhi + 16 * TCP;                                            \
        float av[8] = {a4_0.x, a4_0.y, a4_0.z, a4_0.w, a4_1.x, a4_1.y, a4_1.z, a4_1.w}; \
        _Pragma("unroll")                                                            \
        for (int i = 0; i < 8; i++) {                                                \
            uint32_t hi = f2tf32(av[i]);                                             \
            uint32_t lo = f2tf32(av[i] - __uint_as_float(hi));                       \
            sAhi[(ak + i) * TCP + ar] = hi;                                          \
            sAlo[(ak + i) * TCP + ar] = lo;                                          \
        }                                                                            \
        float bv0[4] = {b4_0.x, b4_0.y, b4_0.z, b4_0.w};                             \
        float bv1[4] = {b4_1.x, b4_1.y, b4_1.z, b4_1.w};                             \
        _Pragma("unroll")                                                            \
        for (int i = 0; i < 4; i++) {                                                \
            uint32_t h0 = f2tf32(bv0[i]);                                            \
            sBhi[bk * TCP + bn4 + i] = h0;                                           \
            sBlo[bk * TCP + bn4 + i] = f2tf32(bv0[i] - __uint_as_float(h0));         \
            uint32_t h1 = f2tf32(bv1[i]);                                            \
            sBhi[(bk + 8) * TCP + bn4 + i] = h1;                                     \
            sBlo[(bk + 8) * TCP + bn4 + i] = f2tf32(bv1[i] - __uint_as_float(h1));   \
        }                                                                            \
    }

    TC_LDG(0); TC_STS(0); __syncthreads();

    const int NST = K / 16;   // 32
    for (int s = 0; s < NST; s++) {
        if (s + 1 < NST) TC_LDG((s + 1) * 16);
        {
            uint32_t* sAhi = smu + (s & 1) * TC_STAGE;
            uint32_t* sAlo = sAhi + 16 * TCP;
            uint32_t* sBhi = sAlo + 16 * TCP;
            uint32_t* sBlo = sBhi + 16 * TCP;
            #pragma unroll
            for (int ks = 0; ks < 16; ks += 8) {
                int ka = (ks + t) * TCP, kb = (ks + t + 4) * TCP;
                uint32_t Ahi[2][4], Alo[2][4], Bhi[8][2], Blo[8][2];
                #pragma unroll
                for (int mi = 0; mi < 2; mi++) {
                    int m = m0w + mi * 16 + g;
                    Ahi[mi][0] = sAhi[ka + m];     Ahi[mi][1] = sAhi[ka + m + 8];
                    Ahi[mi][2] = sAhi[kb + m];     Ahi[mi][3] = sAhi[kb + m + 8];
                    Alo[mi][0] = sAlo[ka + m];     Alo[mi][1] = sAlo[ka + m + 8];
                    Alo[mi][2] = sAlo[kb + m];     Alo[mi][3] = sAlo[kb + m + 8];
                }
                #pragma unroll
                for (int ni = 0; ni < 8; ni++) {
                    int n = n0w + ni * 8 + g;
                    Bhi[ni][0] = sBhi[ka + n];     Bhi[ni][1] = sBhi[kb + n];
                    Blo[ni][0] = sBlo[ka + n];     Blo[ni][1] = sBlo[kb + n];
                }
                #pragma unroll
                for (int mi = 0; mi < 2; mi++)
                    #pragma unroll
                    for (int ni = 0; ni < 8; ni++) {
                        MMA_TF32(acc[mi][ni], Ahi[mi], Bhi[ni]);
                        MMA_TF32(acc[mi][ni], Ahi[mi], Blo[ni]);
                        MMA_TF32(acc[mi][ni], Alo[mi], Bhi[ni]);
                    }
            }
        }
        if (s + 1 < NST) TC_STS((s + 1) & 1);
        __syncthreads();
    }

    // epilogue
    #pragma unroll
    for (int mi = 0; mi < 2; mi++) {
        int m_top = bm + m0w + mi * 16 + g;
        #pragma unroll
        for (int ni = 0; ni < 8; ni++) {
            int n = bn + n0w + ni * 8 + 2 * t;
            float c0 = acc[mi][ni][0], c1 = acc[mi][ni][1];
            float c2 = acc[mi][ni][2], c3 = acc[mi][ni][3];
            if (MODE == 2) {
                float2 bi2 = *(const float2*)&bias[n];
                *(float2*)&C[(size_t)m_top * N + n]       = make_float2(c0 + bi2.x, c1 + bi2.y);
                *(float2*)&C[(size_t)(m_top + 8) * N + n] = make_float2(c2 + bi2.x, c3 + bi2.y);
            } else {
                int h = n >> 6, d = n & 63;
                {
                    int b = m_top >> 12, tp = m_top & 4095;
                    *(float2*)&g_v[(((size_t)(b * 8 + h)) * T + tp) * DH + d] = make_float2(c0, c1);
                }
                {
                    int m2 = m_top + 8;
                    int b = m2 >> 12, tp = m2 & 4095;
                    *(float2*)&g_v[(((size_t)(b * 8 + h)) * T + tp) * DH + d] = make_float2(c2, c3);
                }
            }
        }
    }
#undef TC_LDG
#undef TC_STS
}

// ---------------- hash (rotations + argmax) + stable counting sort ----------------
__global__ void hash_sort_kernel(const float* __restrict__ rotations)
{
    int bh = blockIdx.x >> 2;
    int r  = blockIdx.x & 3;

    __shared__ float rot[64][32];
    __shared__ unsigned char bucket[T];
    __shared__ int hist4[4][NB];
    __shared__ int offs[NB];
    __shared__ int tot[NB];

    int tid = threadIdx.x;
    for (int x = tid; x < 64 * 32; x += 256) {
        int d = x >> 5, i = x & 31;
        rot[d][i] = rotations[(d * NH + r) * 32 + i];
    }
    ((int*)hist4)[tid] = 0;
    __syncthreads();

    const float* qkbh = g_qk + (size_t)bh * T * DH;
    for (int t = tid; t < T; t += 256) {
        const float* q = qkbh + (size_t)t * DH;
        float s[32];
        #pragma unroll
        for (int i = 0; i < 32; i++) s[i] = 0.f;
        for (int d4 = 0; d4 < 16; d4++) {
            float4 qv = *(const float4*)&q[d4 * 4];
            #pragma unroll
            for (int i = 0; i < 32; i++) {
                s[i] = fmaf(qv.x, rot[d4 * 4 + 0][i], s[i]);
                s[i] = fmaf(qv.y, rot[d4 * 4 + 1][i], s[i]);
                s[i] = fmaf(qv.z, rot[d4 * 4 + 2][i], s[i]);
                s[i] = fmaf(qv.w, rot[d4 * 4 + 3][i], s[i]);
            }
        }
        float best = -3.4e38f; int bi = 0;
        #pragma unroll
        for (int i = 0; i < 32; i++) { if (s[i] > best) { best = s[i]; bi = i; } }
        #pragma unroll
        for (int i = 0; i < 32; i++) { float v = -s[i]; if (v > best) { best = v; bi = 32 + i; } }
        bucket[t] = (unsigned char)bi;
        atomicAdd(&hist4[t >> 10][bi], 1);
    }
    __syncthreads();

    if (tid < NB)
        tot[tid] = hist4[0][tid] + hist4[1][tid] + hist4[2][tid] + hist4[3][tid];
    __syncthreads();
    if (tid == 0) {
        int run = 0;
        for (int b = 0; b < NB; b++) { offs[b] = run; run += tot[b]; }
    }
    __syncthreads();

    {
        int b = tid & 63, q = tid >> 6;
        int o = offs[b];
        #pragma unroll
        for (int qq = 0; qq < 3; qq++) if (qq < q) o += hist4[qq][b];
        int* stout = g_st + (bh * NH + r) * T;
        int t0 = q << 10;
        for (int t = t0; t < t0 + 1024; t++) {
            if (bucket[t] == (unsigned char)b) stout[o++] = t;
        }
    }
}

// ---------------- chunked LSH attention (conflict-free layout) ----------------
#define KTP 136
#define VP  68
#define DP  132
#define SMEM_ATTN ((64*KTP + 128*VP + 128 + 64 + 128) * 4)

__global__ __launch_bounds__(256, 3)
void lsh_attn_kernel()
{
    int bh = blockIdx.x >> 8;
    int c  = blockIdx.x & 255;
    int r  = c >> 6;
    int pc = (c + 255) & 255;

    float* Kt       = smem;                      // 64 x KTP   (Kt[k][row])
    float* Vs       = Kt + 64 * KTP;             // 128 x VP
    float* inv_norm = Vs + 128 * VP;             // 128
    float* invs     = inv_norm + 128;            // 64
    int*   kpos     = (int*)(invs + 64);         // 128
    float* dots     = Kt;                        // overlay: 64 x DP

    int tid = threadIdx.x;
    if (tid < 128) {
        int g = (tid < 64) ? (c * 64 + tid) : (pc * 64 + tid - 64);
        kpos[tid] = g_st[bh * (NH * T) + g];
    }
    __syncthreads();

    {
        int row  = tid >> 1;
        int half = (tid & 1) << 5;
        int p = kpos[row];
        const float* ksrc = g_qk + ((size_t)bh * T + p) * DH + half;
        const float* vsrc = g_v  + ((size_t)bh * T + p) * DH + half;
        float ss = 0.f;
        #pragma unroll
        for (int u = 0; u < 8; u++) {
            float4 kv = *(const float4*)&ksrc[u * 4];
            float4 vv = *(const float4*)&vsrc[u * 4];
            int k = half + u * 4;
            Kt[(k + 0) * KTP + row] = kv.x;
            Kt[(k + 1) * KTP + row] = kv.y;
            Kt[(k + 2) * KTP + row] = kv.z;
            Kt[(k + 3) * KTP + row] = kv.w;
            *(float4*)&Vs[row * VP + k] = vv;
            ss = fmaf(kv.x, kv.x, ss); ss = fmaf(kv.y, kv.y, ss);
            ss = fmaf(kv.z, kv.z, ss); ss = fmaf(kv.w, kv.w, ss);
        }
        ss += __shfl_xor_sync(0xffffffffu, ss, 1);
        if ((tid & 1) == 0)
            inv_norm[row] = 1.0f / fmaxf(sqrtf(ss), 1e-12f);
    }
    __syncthreads();

    int tx = tid & 15, ty = tid >> 4;
    int i0 = ty * 4;

    float qkacc[4][8] = {};
    #pragma unroll 4
    for (int k = 0; k < 64; k++) {
        const float* krow = Kt + k * KTP;
        float4 a = *(const float4*)&krow[i0];
        float2 b0 = *(const float2*)&krow[2 * tx];
        float2 b1 = *(const float2*)&krow[2 * tx + 32];
        float2 b2 = *(const float2*)&krow[2 * tx + 64];
        float2 b3 = *(const float2*)&krow[2 * tx + 96];
        float av[4] = {a.x, a.y, a.z, a.w};
        float bv[8] = {b0.x, b0.y, b1.x, b1.y, b2.x, b2.y, b3.x, b3.y};
        #pragma unroll
        for (int i = 0; i < 4; i++)
            #pragma unroll
            for (int j = 0; j < 8; j++)
                qkacc[i][j] = fmaf(av[i], bv[j], qkacc[i][j]);
    }

    float inj[8];
    int   pj[8];
    #pragma unroll
    for (int g = 0; g < 4; g++) {
        int j = 2 * tx + 32 * g;
        inj[2 * g]     = inv_norm[j];     pj[2 * g]     = kpos[j];
        inj[2 * g + 1] = inv_norm[j + 1]; pj[2 * g + 1] = kpos[j + 1];
    }
    #pragma unroll
    for (int i = 0; i < 4; i++) {
        int qp = kpos[i0 + i];
        #pragma unroll
        for (int j = 0; j < 8; j++) {
            float v = qkacc[i][j] * inj[j] * 0.125f;
            qkacc[i][j] = (pj[j] == qp) ? SELF_VAL : v;
        }
    }
    __syncthreads();

    #pragma unroll
    for (int i = 0; i < 4; i++) {
        float* drow = dots + (i0 + i) * DP;
        #pragma unroll
        for (int g = 0; g < 4; g++)
            *(float2*)&drow[2 * tx + 32 * g] =
                make_float2(qkacc[i][2 * g], qkacc[i][2 * g + 1]);
    }
    __syncthreads();

    {
        int row = tid >> 2, seg = tid & 3;
        float* drow = dots + row * DP;
        float mp = -3.4e38f;
        #pragma unroll
        for (int k = 0; k < 32; k++) mp = fmaxf(mp, drow[seg + 4 * k]);
        mp = fmaxf(mp, __shfl_xor_sync(0xffffffffu, mp, 1));
        mp = fmaxf(mp, __shfl_xor_sync(0xffffffffu, mp, 2));
        float sp = 0.f;
        #pragma unroll
        for (int k = 0; k < 32; k++) {
            float e = __expf(drow[seg + 4 * k] - mp);
            drow[seg + 4 * k] = e;
            sp += e;
        }
        sp += __shfl_xor_sync(0xffffffffu, sp, 1);
        sp += __shfl_xor_sync(0xffffffffu, sp, 2);
        if (seg == 0) {
            invs[row] = 1.0f / sp;
            g_lse[((size_t)bh * NH + r) * T + kpos[row]] = mp + logf(sp);
        }
    }
    __syncthreads();

    {
        float acc[4][4] = {};
        #pragma unroll 2
        for (int k = 0; k < 128; k += 2) {
            float2 ap[4];
            #pragma unroll
            for (int i = 0; i < 4; i++)
                ap[i] = *(const float2*)&dots[(i0 + i) * DP + k];
            float2 v00 = *(const float2*)&Vs[k * VP + 2 * tx];
            float2 v01 = *(const float2*)&Vs[k * VP + 2 * tx + 32];
            float2 v10 = *(const float2*)&Vs[(k + 1) * VP + 2 * tx];
            float2 v11 = *(const float2*)&Vs[(k + 1) * VP + 2 * tx + 32];
            #pragma unroll
            for (int i = 0; i < 4; i++) {
                acc[i][0] = fmaf(ap[i].x, v00.x, acc[i][0]);
                acc[i][1] = fmaf(ap[i].x, v00.y, acc[i][1]);
                acc[i][2] = fmaf(ap[i].x, v01.x, acc[i][2]);
                acc[i][3] = fmaf(ap[i].x, v01.y, acc[i][3]);
                acc[i][0] = fmaf(ap[i].y, v10.x, acc[i][0]);
                acc[i][1] = fmaf(ap[i].y, v10.y, acc[i][1]);
                acc[i][2] = fmaf(ap[i].y, v11.x, acc[i][2]);
                acc[i][3] = fmaf(ap[i].y, v11.y, acc[i][3]);
            }
        }
        #pragma unroll
        for (int i = 0; i < 4; i++) {
            float sc = invs[i0 + i];
            size_t base = (((size_t)bh * NH + r) * T + kpos[i0 + i]) * DH;
            *(float2*)&g_o[base + 2 * tx]      = make_float2(acc[i][0] * sc, acc[i][1] * sc);
            *(float2*)&g_o[base + 2 * tx + 32] = make_float2(acc[i][2] * sc, acc[i][3] * sc);
        }
    }
}

// ---------------- combine hash rounds ----------------
__global__ void combine_kernel()
{
    int idx = blockIdx.x * 256 + threadIdx.x;
    int d   = idx & 63;
    int pos = (idx >> 6) & 4095;
    int bh  = idx >> 18;

    float l[4];
    #pragma unroll
    for (int r = 0; r < 4; r++) l[r] = g_lse[((size_t)bh * 4 + r) * T + pos];
    float m = fmaxf(fmaxf(l[0], l[1]), fmaxf(l[2], l[3]));
    float w[4], ws = 0.f;
    #pragma unroll
    for (int r = 0; r < 4; r++) { w[r] = __expf(l[r] - m); ws += w[r]; }
    float o = 0.f;
    #pragma unroll
    for (int r = 0; r < 4; r++)
        o += w[r] * g_o[(((size_t)bh * 4 + r) * T + pos) * DH + d];
    o /= ws;

    int b = bh >> 3, h = bh & 7;
    g_ctx[((size_t)b * T + pos) * DM + h * 64 + d] = o;
}

// ---------------- launch ----------------
extern "C" void kernel_launch(void* const* d_in, const int* in_sizes, int n_in,
                              void* d_out, int out_size)
{
    (void)in_sizes; (void)n_in; (void)out_size;
    const float* queries   = (const float*)d_in[0];
    const float* W_qk      = (const float*)d_in[3];
    const float* W_v       = (const float*)d_in[4];
    const float* W_out     = (const float*)d_in[5];
    const float* b_out     = (const float*)d_in[6];
    const float* rotations = (const float*)d_in[7];
    float* out = (float*)d_out;

    dim3 gq(512 / 64, 16384 / 128);    // fp32 qk gemm
    dim3 gt(512 / 128, 16384 / 128);   // tensor-core gemms

    cudaFuncSetAttribute(gemm_tc_kernel<1>,
                         cudaFuncAttributeMaxDynamicSharedMemorySize, SMEM_TC);
    cudaFuncSetAttribute(gemm_tc_kernel<2>,
                         cudaFuncAttributeMaxDynamicSharedMemorySize, SMEM_TC);
    cudaFuncSetAttribute(lsh_attn_kernel,
                         cudaFuncAttributeMaxDynamicSharedMemorySize, SMEM_ATTN);

    gemm_qk_kernel<<<gq, 256>>>(queries, W_qk);
    gemm_tc_kernel<1><<<gt, 256, SMEM_TC>>>(queries, W_v, nullptr, nullptr);

    hash_sort_kernel<<<BHN * NH, 256>>>(rotations);

    lsh_attn_kernel<<<BHN * 256, 256, SMEM_ATTN>>>();

    combine_kernel<<<(BHN * T * DH) / 256, 256>>>();

    gemm_tc_kernel<2><<<gt, 256, SMEM_TC>>>(nullptr, W_out, b_out, out);
}

// round 6
// speedup vs baseline: 1.0634x; 1.0634x over previous
#include <cuda_runtime.h>
#include <math.h>
#include <stdint.h>

// Problem constants
#define T      4096
#define DH     64
#define NH     4        // n_hashes
#define NB     64       // buckets per hash
#define DM     512
#define BHN    32       // B*H
#define SELF_VAL (-5e4f)

// ---------------- scratch (device globals; no allocation allowed) ----------------
__device__ float g_qk [(size_t)BHN * T * DH];        // merged qk  (bh, t, dh)
__device__ float g_v  [(size_t)BHN * T * DH];        // merged v
__device__ int   g_st [BHN * NH * T];                // sorted original positions
__device__ float g_o  [(size_t)BHN * NH * T * DH];   // per-round outputs
__device__ float g_lse[BHN * NH * T];                // per-round logsumexp
__device__ float g_ctx[(size_t)4 * T * DM];          // combined context (B,T,DM)

extern __shared__ float smem[];

// ---------------- packed fp32x2 helpers (Blackwell FFMA2; exact per-lane fp32) ----
__device__ __forceinline__ unsigned long long bcast2(float x) {
    unsigned long long r;
    asm("mov.b64 %0, {%1, %1};" : "=l"(r) : "f"(x));
    return r;
}
__device__ __forceinline__ float2 unpk2(unsigned long long v) {
    float2 f;
    asm("mov.b64 {%0, %1}, %2;" : "=f"(f.x), "=f"(f.y) : "l"(v));
    return f;
}
#define FMA2(d, a, b) \
    asm("fma.rn.f32x2 %0, %1, %2, %0;" : "+l"(d) : "l"(a), "l"(b))

// ---------------- fp32 GEMM via FFMA2 (W_qk: feeds hash argmax, exact fp32) -------
__global__ __launch_bounds__(256)
void gemm_qk_kernel(const float* __restrict__ A,
                    const float* __restrict__ Bm)
{
    const int N = 512, K = 512;
    __shared__ float As[2][16][132];   // [k][m]
    __shared__ float Bs[2][16][68];    // [k][n]

    int tid = threadIdx.x;
    int tx = tid & 15, ty = tid >> 4;
    int bm = blockIdx.y * 128, bn = blockIdx.x * 64;

    int f0 = tid * 2, f1 = tid * 2 + 1;
    int a_row0 = f0 >> 2, a_k0 = (f0 & 3) << 2;
    int a_row1 = f1 >> 2, a_k1 = (f1 & 3) << 2;
    int b_k = tid >> 4, b_n = (tid & 15) << 2;

    float4 ar0, ar1, br;
    unsigned long long acc2[8][2];
    #pragma unroll
    for (int i = 0; i < 8; i++) { acc2[i][0] = 0ull; acc2[i][1] = 0ull; }

#define LDG_TILE(k0)                                                              \
    {   ar0 = *(const float4*)&A[(size_t)(bm + a_row0) * K + (k0) + a_k0];        \
        ar1 = *(const float4*)&A[(size_t)(bm + a_row1) * K + (k0) + a_k1];        \
        br  = *(const float4*)&Bm[(size_t)((k0) + b_k) * N + bn + b_n]; }
#define STS_TILE(buf)                                                             \
    {   As[buf][a_k0 + 0][a_row0] = ar0.x; As[buf][a_k0 + 1][a_row0] = ar0.y;     \
        As[buf][a_k0 + 2][a_row0] = ar0.z; As[buf][a_k0 + 3][a_row0] = ar0.w;     \
        As[buf][a_k1 + 0][a_row1] = ar1.x; As[buf][a_k1 + 1][a_row1] = ar1.y;     \
        As[buf][a_k1 + 2][a_row1] = ar1.z; As[buf][a_k1 + 3][a_row1] = ar1.w;     \
        *(float4*)&Bs[buf][b_k][b_n] = br; }

    LDG_TILE(0); STS_TILE(0); __syncthreads();

    const int NST = K / 16;   // 32
    for (int s = 0; s < NST; s++) {
        if (s + 1 < NST) LDG_TILE((s + 1) * 16);
        int buf = s & 1;
        #pragma unroll
        for (int k = 0; k < 16; k++) {
            float4 a0 = *(const float4*)&As[buf][k][ty * 8];
            float4 a1 = *(const float4*)&As[buf][k][ty * 8 + 4];
            ulonglong2 b2 = *(const ulonglong2*)&Bs[buf][k][tx * 4];
            float av[8] = {a0.x, a0.y, a0.z, a0.w, a1.x, a1.y, a1.z, a1.w};
            #pragma unroll
            for (int i = 0; i < 8; i++) {
                unsigned long long ap = bcast2(av[i]);
                FMA2(acc2[i][0], ap, b2.x);
                FMA2(acc2[i][1], ap, b2.y);
            }
        }
        if (s + 1 < NST) STS_TILE((s + 1) & 1);
        __syncthreads();
    }

    #pragma unroll
    for (int i = 0; i < 8; i++) {
        int m = bm + ty * 8 + i;
        float2 p0 = unpk2(acc2[i][0]), p1 = unpk2(acc2[i][1]);
        float vv[4] = {p0.x, p0.y, p1.x, p1.y};
        #pragma unroll
        for (int j = 0; j < 4; j++) {
            int n = bn + tx * 4 + j;
            int b = m >> 12, t = m & 4095;
            int h = n >> 6,  d = n & 63;
            g_qk[(((size_t)(b * 8 + h)) * T + t) * DH + d] = vv[j];
        }
    }
#undef LDG_TILE
#undef STS_TILE
}

// ---------------- 3xTF32 tensor-core GEMM (W_v merged / W_out + bias) -------------
__device__ __forceinline__ uint32_t f2tf32(float x) {
    uint32_t u; asm("cvt.rna.tf32.f32 %0, %1;" : "=r"(u) : "f"(x)); return u;
}

#define MMA_TF32(c, a, b)                                                          \
    asm volatile("mma.sync.aligned.m16n8k8.row.col.f32.tf32.tf32.f32 "             \
                 "{%0,%1,%2,%3},{%4,%5,%6,%7},{%8,%9},{%0,%1,%2,%3};"              \
                 : "+f"(c[0]), "+f"(c[1]), "+f"(c[2]), "+f"(c[3])                  \
                 : "r"(a[0]), "r"(a[1]), "r"(a[2]), "r"(a[3]), "r"(b[0]), "r"(b[1]))

#define TCP 136
#define TC_STAGE (4 * 16 * TCP)
#define SMEM_TC (2 * TC_STAGE * 4)

// MODE 1: write g_v merged; MODE 2: C = acc + bias
template <int MODE>
__global__ __launch_bounds__(256)
void gemm_tc_kernel(const float* __restrict__ A,
                    const float* __restrict__ Bm,
                    const float* __restrict__ bias,
                    float* __restrict__ C)
{
    const int K = 512, N = 512;
    const float* Ap = (MODE == 2) ? g_ctx : A;

    int tid = threadIdx.x, lane = tid & 31, wid = tid >> 5;
    int wm = wid >> 1, wn = wid & 1;
    int m0w = wm * 32, n0w = wn * 64;
    int g = lane >> 2, t = lane & 3;
    int bm = blockIdx.y * 128, bn = blockIdx.x * 128;

    int ar = tid >> 1, ak = (tid & 1) * 8;
    int bk = tid >> 5, bn4 = (tid & 31) * 4;

    uint32_t* smu = (uint32_t*)smem;
    float4 a4_0, a4_1, b4_0, b4_1;
    float acc[2][8][4] = {};

#define TC_LDG(k0)                                                                   \
    {   a4_0 = *(const float4*)&Ap[(size_t)(bm + ar) * K + (k0) + ak];               \
        a4_1 = *(const float4*)&Ap[(size_t)(bm + ar) * K + (k0) + ak + 4];           \
        b4_0 = *(const float4*)&Bm[(size_t)((k0) + bk) * N + bn + bn4];              \
        b4_1 = *(const float4*)&Bm[(size_t)((k0) + bk + 8) * N + bn + bn4]; }

#define TC_STS(s)                                                                    \
    {   uint32_t* sAhi = smu + (s) * TC_STAGE;                                       \
        uint32_t* sAlo = sAhi + 16 * TCP;                                            \
        uint32_t* sBhi = sAlo + 16 * TCP;                                            \
        uint32_t* sBlo = sBhi + 16 * TCP;                                            \
        float av[8] = {a4_0.x, a4_0.y, a4_0.z, a4_0.w, a4_1.x, a4_1.y, a4_1.z, a4_1.w}; \
        _Pragma("unroll")                                                            \
        for (int i = 0; i < 8; i++) {                                                \
            uint32_t hi = f2tf32(av[i]);                                             \
            uint32_t lo = f2tf32(av[i] - __uint_as_float(hi));                       \
            sAhi[(ak + i) * TCP + ar] = hi;                                          \
            sAlo[(ak + i) * TCP + ar] = lo;                                          \
        }                                                                            \
        float bv0[4] = {b4_0.x, b4_0.y, b4_0.z, b4_0.w};                             \
        float bv1[4] = {b4_1.x, b4_1.y, b4_1.z, b4_1.w};                             \
        _Pragma("unroll")                                                            \
        for (int i = 0; i < 4; i++) {                                                \
            uint32_t h0 = f2tf32(bv0[i]);                                            \
            sBhi[bk * TCP + bn4 + i] = h0;                                           \
            sBlo[bk * TCP + bn4 + i] = f2tf32(bv0[i] - __uint_as_float(h0));         \
            uint32_t h1 = f2tf32(bv1[i]);                                            \
            sBhi[(bk + 8) * TCP + bn4 + i] = h1;                                     \
            sBlo[(bk + 8) * TCP + bn4 + i] = f2tf32(bv1[i] - __uint_as_float(h1));   \
        }                                                                            \
    }

    TC_LDG(0); TC_STS(0); __syncthreads();

    const int NST = K / 16;   // 32
    for (int s = 0; s < NST; s++) {
        if (s + 1 < NST) TC_LDG((s + 1) * 16);
        {
            uint32_t* sAhi = smu + (s & 1) * TC_STAGE;
            uint32_t* sAlo = sAhi + 16 * TCP;
            uint32_t* sBhi = sAlo + 16 * TCP;
            uint32_t* sBlo = sBhi + 16 * TCP;
            #pragma unroll
            for (int ks = 0; ks < 16; ks += 8) {
                int ka = (ks + t) * TCP, kb = (ks + t + 4) * TCP;
                uint32_t Ahi[2][4], Alo[2][4], Bhi[8][2], Blo[8][2];
                #pragma unroll
                for (int mi = 0; mi < 2; mi++) {
                    int m = m0w + mi * 16 + g;
                    Ahi[mi][0] = sAhi[ka + m];     Ahi[mi][1] = sAhi[ka + m + 8];
                    Ahi[mi][2] = sAhi[kb + m];     Ahi[mi][3] = sAhi[kb + m + 8];
                    Alo[mi][0] = sAlo[ka + m];     Alo[mi][1] = sAlo[ka + m + 8];
                    Alo[mi][2] = sAlo[kb + m];     Alo[mi][3] = sAlo[kb + m + 8];
                }
                #pragma unroll
                for (int ni = 0; ni < 8; ni++) {
                    int n = n0w + ni * 8 + g;
                    Bhi[ni][0] = sBhi[ka + n];     Bhi[ni][1] = sBhi[kb + n];
                    Blo[ni][0] = sBlo[ka + n];     Blo[ni][1] = sBlo[kb + n];
                }
                #pragma unroll
                for (int mi = 0; mi < 2; mi++)
                    #pragma unroll
                    for (int ni = 0; ni < 8; ni++) {
                        MMA_TF32(acc[mi][ni], Ahi[mi], Bhi[ni]);
                        MMA_TF32(acc[mi][ni], Ahi[mi], Blo[ni]);
                        MMA_TF32(acc[mi][ni], Alo[mi], Bhi[ni]);
                    }
            }
        }
        if (s + 1 < NST) TC_STS((s + 1) & 1);
        __syncthreads();
    }

    #pragma unroll
    for (int mi = 0; mi < 2; mi++) {
        int m_top = bm + m0w + mi * 16 + g;
        #pragma unroll
        for (int ni = 0; ni < 8; ni++) {
            int n = bn + n0w + ni * 8 + 2 * t;
            float c0 = acc[mi][ni][0], c1 = acc[mi][ni][1];
            float c2 = acc[mi][ni][2], c3 = acc[mi][ni][3];
            if (MODE == 2) {
                float2 bi2 = *(const float2*)&bias[n];
                *(float2*)&C[(size_t)m_top * N + n]       = make_float2(c0 + bi2.x, c1 + bi2.y);
                *(float2*)&C[(size_t)(m_top + 8) * N + n] = make_float2(c2 + bi2.x, c3 + bi2.y);
            } else {
                int h = n >> 6, d = n & 63;
                {
                    int b = m_top >> 12, tp = m_top & 4095;
                    *(float2*)&g_v[(((size_t)(b * 8 + h)) * T + tp) * DH + d] = make_float2(c0, c1);
                }
                {
                    int m2 = m_top + 8;
                    int b = m2 >> 12, tp = m2 & 4095;
                    *(float2*)&g_v[(((size_t)(b * 8 + h)) * T + tp) * DH + d] = make_float2(c2, c3);
                }
            }
        }
    }
#undef TC_LDG
#undef TC_STS
}

// ---------------- hash (rotations + argmax) + stable counting sort ----------------
__global__ void hash_sort_kernel(const float* __restrict__ rotations)
{
    int bh = blockIdx.x >> 2;
    int r  = blockIdx.x & 3;

    __shared__ float rot[64][32];
    __shared__ unsigned char bucket[T];
    __shared__ int hist4[4][NB];
    __shared__ int offs[NB];
    __shared__ int tot[NB];

    int tid = threadIdx.x;
    for (int x = tid; x < 64 * 32; x += 256) {
        int d = x >> 5, i = x & 31;
        rot[d][i] = rotations[(d * NH + r) * 32 + i];
    }
    ((int*)hist4)[tid] = 0;
    __syncthreads();

    const float* qkbh = g_qk + (size_t)bh * T * DH;
    for (int t = tid; t < T; t += 256) {
        const float* q = qkbh + (size_t)t * DH;
        float s[32];
        #pragma unroll
        for (int i = 0; i < 32; i++) s[i] = 0.f;
        for (int d4 = 0; d4 < 16; d4++) {
            float4 qv = *(const float4*)&q[d4 * 4];
            #pragma unroll
            for (int i = 0; i < 32; i++) {
                s[i] = fmaf(qv.x, rot[d4 * 4 + 0][i], s[i]);
                s[i] = fmaf(qv.y, rot[d4 * 4 + 1][i], s[i]);
                s[i] = fmaf(qv.z, rot[d4 * 4 + 2][i], s[i]);
                s[i] = fmaf(qv.w, rot[d4 * 4 + 3][i], s[i]);
            }
        }
        float best = -3.4e38f; int bi = 0;
        #pragma unroll
        for (int i = 0; i < 32; i++) { if (s[i] > best) { best = s[i]; bi = i; } }
        #pragma unroll
        for (int i = 0; i < 32; i++) { float v = -s[i]; if (v > best) { best = v; bi = 32 + i; } }
        bucket[t] = (unsigned char)bi;
        atomicAdd(&hist4[t >> 10][bi], 1);
    }
    __syncthreads();

    if (tid < NB)
        tot[tid] = hist4[0][tid] + hist4[1][tid] + hist4[2][tid] + hist4[3][tid];
    __syncthreads();
    if (tid == 0) {
        int run = 0;
        for (int b = 0; b < NB; b++) { offs[b] = run; run += tot[b]; }
    }
    __syncthreads();

    {
        int b = tid & 63, q = tid >> 6;
        int o = offs[b];
        #pragma unroll
        for (int qq = 0; qq < 3; qq++) if (qq < q) o += hist4[qq][b];
        int* stout = g_st + (bh * NH + r) * T;
        int t0 = q << 10;
        for (int t = t0; t < t0 + 1024; t++) {
            if (bucket[t] == (unsigned char)b) stout[o++] = t;
        }
    }
}

// ---------------- chunked LSH attention (conflict-free + FFMA2) -------------------
#define KTP 136
#define VP  68
#define DP  132
#define SMEM_ATTN ((64*KTP + 128*VP + 128 + 64 + 128) * 4)

__global__ __launch_bounds__(256, 3)
void lsh_attn_kernel()
{
    int bh = blockIdx.x >> 8;
    int c  = blockIdx.x & 255;
    int r  = c >> 6;
    int pc = (c + 255) & 255;

    float* Kt       = smem;                      // 64 x KTP   (Kt[k][row])
    float* Vs       = Kt + 64 * KTP;             // 128 x VP
    float* inv_norm = Vs + 128 * VP;             // 128
    float* invs     = inv_norm + 128;            // 64
    int*   kpos     = (int*)(invs + 64);         // 128
    float* dots     = Kt;                        // overlay: 64 x DP

    int tid = threadIdx.x;
    if (tid < 128) {
        int g = (tid < 64) ? (c * 64 + tid) : (pc * 64 + tid - 64);
        kpos[tid] = g_st[bh * (NH * T) + g];
    }
    __syncthreads();

    {
        int row  = tid >> 1;
        int half = (tid & 1) << 5;
        int p = kpos[row];
        const float* ksrc = g_qk + ((size_t)bh * T + p) * DH + half;
        const float* vsrc = g_v  + ((size_t)bh * T + p) * DH + half;
        float ss = 0.f;
        #pragma unroll
        for (int u = 0; u < 8; u++) {
            float4 kv = *(const float4*)&ksrc[u * 4];
            float4 vv = *(const float4*)&vsrc[u * 4];
            int k = half + u * 4;
            Kt[(k + 0) * KTP + row] = kv.x;
            Kt[(k + 1) * KTP + row] = kv.y;
            Kt[(k + 2) * KTP + row] = kv.z;
            Kt[(k + 3) * KTP + row] = kv.w;
            *(float4*)&Vs[row * VP + k] = vv;
            ss = fmaf(kv.x, kv.x, ss); ss = fmaf(kv.y, kv.y, ss);
            ss = fmaf(kv.z, kv.z, ss); ss = fmaf(kv.w, kv.w, ss);
        }
        ss += __shfl_xor_sync(0xffffffffu, ss, 1);
        if ((tid & 1) == 0)
            inv_norm[row] = 1.0f / fmaxf(sqrtf(ss), 1e-12f);
    }
    __syncthreads();

    int tx = tid & 15, ty = tid >> 4;
    int i0 = ty * 4;
    // j columns: {4tx+u : u=0..3} U {64+4tx+u : u=0..3}

    // ---- QK^T with packed FFMA2
    unsigned long long acc2[4][4];
    #pragma unroll
    for (int i = 0; i < 4; i++)
        #pragma unroll
        for (int p = 0; p < 4; p++) acc2[i][p] = 0ull;

    #pragma unroll 4
    for (int k = 0; k < 64; k++) {
        const float* krow = Kt + k * KTP;
        float4 a = *(const float4*)&krow[i0];
        ulonglong2 bA = *(const ulonglong2*)&krow[4 * tx];
        ulonglong2 bB = *(const ulonglong2*)&krow[64 + 4 * tx];
        float av[4] = {a.x, a.y, a.z, a.w};
        #pragma unroll
        for (int i = 0; i < 4; i++) {
            unsigned long long ap = bcast2(av[i]);
            FMA2(acc2[i][0], ap, bA.x);
            FMA2(acc2[i][1], ap, bA.y);
            FMA2(acc2[i][2], ap, bB.x);
            FMA2(acc2[i][3], ap, bB.y);
        }
    }

    // scale + self-mask in registers
    float4 in0 = *(const float4*)&inv_norm[4 * tx];
    float4 in1 = *(const float4*)&inv_norm[64 + 4 * tx];
    int4   kp0 = *(const int4*)&kpos[4 * tx];
    int4   kp1 = *(const int4*)&kpos[64 + 4 * tx];
    float inj[8] = {in0.x, in0.y, in0.z, in0.w, in1.x, in1.y, in1.z, in1.w};
    int   pj[8]  = {kp0.x, kp0.y, kp0.z, kp0.w, kp1.x, kp1.y, kp1.z, kp1.w};

    float m8[4][8];
    #pragma unroll
    for (int i = 0; i < 4; i++) {
        int qp = kpos[i0 + i];
        float2 p0 = unpk2(acc2[i][0]), p1 = unpk2(acc2[i][1]);
        float2 p2 = unpk2(acc2[i][2]), p3 = unpk2(acc2[i][3]);
        float vj[8] = {p0.x, p0.y, p1.x, p1.y, p2.x, p2.y, p3.x, p3.y};
        #pragma unroll
        for (int j = 0; j < 8; j++) {
            float v = vj[j] * inj[j] * 0.125f;
            m8[i][j] = (pj[j] == qp) ? SELF_VAL : v;
        }
    }
    __syncthreads();   // all Kt reads done -> overlay with dots

    #pragma unroll
    for (int i = 0; i < 4; i++) {
        float* drow = dots + (i0 + i) * DP;
        *(float4*)&drow[4 * tx]      = make_float4(m8[i][0], m8[i][1], m8[i][2], m8[i][3]);
        *(float4*)&drow[64 + 4 * tx] = make_float4(m8[i][4], m8[i][5], m8[i][6], m8[i][7]);
    }
    __syncthreads();

    // ---- softmax: thread -> (row = tid>>2, seg = tid&3); shuffle reduce within quad
    {
        int row = tid >> 2, seg = tid & 3;
        float* drow = dots + row * DP;
        float mp = -3.4e38f;
        #pragma unroll
        for (int k = 0; k < 32; k++) mp = fmaxf(mp, drow[seg + 4 * k]);
        mp = fmaxf(mp, __shfl_xor_sync(0xffffffffu, mp, 1));
        mp = fmaxf(mp, __shfl_xor_sync(0xffffffffu, mp, 2));
        float sp = 0.f;
        #pragma unroll
        for (int k = 0; k < 32; k++) {
            float e = __expf(drow[seg + 4 * k] - mp);
            drow[seg + 4 * k] = e;
            sp += e;
        }
        sp += __shfl_xor_sync(0xffffffffu, sp, 1);
        sp += __shfl_xor_sync(0xffffffffu, sp, 2);
        if (seg == 0) {
            invs[row] = 1.0f / sp;
            g_lse[((size_t)bh * NH + r) * T + kpos[row]] = mp + logf(sp);
        }
    }
    __syncthreads();

    // ---- PV with packed FFMA2: d cols = {4tx..4tx+3}
    {
        unsigned long long pv2[4][2];
        #pragma unroll
        for (int i = 0; i < 4; i++) { pv2[i][0] = 0ull; pv2[i][1] = 0ull; }

        #pragma unroll 2
        for (int k = 0; k < 128; k += 2) {
            float2 pr[4];
            #pragma unroll
            for (int i = 0; i < 4; i++)
                pr[i] = *(const float2*)&dots[(i0 + i) * DP + k];
            ulonglong2 v0 = *(const ulonglong2*)&Vs[k * VP + 4 * tx];
            ulonglong2 v1 = *(const ulonglong2*)&Vs[(k + 1) * VP + 4 * tx];
            #pragma unroll
            for (int i = 0; i < 4; i++) {
                unsigned long long pa = bcast2(pr[i].x);
                FMA2(pv2[i][0], pa, v0.x);
                FMA2(pv2[i][1], pa, v0.y);
                unsigned long long pb = bcast2(pr[i].y);
                FMA2(pv2[i][0], pb, v1.x);
                FMA2(pv2[i][1], pb, v1.y);
            }
        }
        #pragma unroll
        for (int i = 0; i < 4; i++) {
            float sc = invs[i0 + i];
            float2 a = unpk2(pv2[i][0]), b = unpk2(pv2[i][1]);
            size_t base = (((size_t)bh * NH + r) * T + kpos[i0 + i]) * DH;
            *(float4*)&g_o[base + 4 * tx] =
                make_float4(a.x * sc, a.y * sc, b.x * sc, b.y * sc);
        }
    }
}

// ---------------- combine hash rounds ----------------
__global__ void combine_kernel()
{
    int idx = blockIdx.x * 256 + threadIdx.x;
    int d   = idx & 63;
    int pos = (idx >> 6) & 4095;
    int bh  = idx >> 18;

    float l[4];
    #pragma unroll
    for (int r = 0; r < 4; r++) l[r] = g_lse[((size_t)bh * 4 + r) * T + pos];
    float m = fmaxf(fmaxf(l[0], l[1]), fmaxf(l[2], l[3]));
    float w[4], ws = 0.f;
    #pragma unroll
    for (int r = 0; r < 4; r++) { w[r] = __expf(l[r] - m); ws += w[r]; }
    float o = 0.f;
    #pragma unroll
    for (int r = 0; r < 4; r++)
        o += w[r] * g_o[(((size_t)bh * 4 + r) * T + pos) * DH + d];
    o /= ws;

    int b = bh >> 3, h = bh & 7;
    g_ctx[((size_t)b * T + pos) * DM + h * 64 + d] = o;
}

// ---------------- launch ----------------
extern "C" void kernel_launch(void* const* d_in, const int* in_sizes, int n_in,
                              void* d_out, int out_size)
{
    (void)in_sizes; (void)n_in; (void)out_size;
    const float* queries   = (const float*)d_in[0];
    const float* W_qk      = (const float*)d_in[3];
    const float* W_v       = (const float*)d_in[4];
    const float* W_out     = (const float*)d_in[5];
    const float* b_out     = (const float*)d_in[6];
    const float* rotations = (const float*)d_in[7];
    float* out = (float*)d_out;

    static cudaStream_t s_aux = nullptr;
    static cudaEvent_t ev_fork = nullptr, ev_join = nullptr;
    if (!s_aux) {
        cudaStreamCreateWithFlags(&s_aux, cudaStreamNonBlocking);
        cudaEventCreateWithFlags(&ev_fork, cudaEventDisableTiming);
        cudaEventCreateWithFlags(&ev_join, cudaEventDisableTiming);
    }

    dim3 gq(512 / 64, 16384 / 128);    // fp32 qk gemm
    dim3 gt(512 / 128, 16384 / 128);   // tensor-core gemms

    cudaFuncSetAttribute(gemm_tc_kernel<1>,
                         cudaFuncAttributeMaxDynamicSharedMemorySize, SMEM_TC);
    cudaFuncSetAttribute(gemm_tc_kernel<2>,
                         cudaFuncAttributeMaxDynamicSharedMemorySize, SMEM_TC);
    cudaFuncSetAttribute(lsh_attn_kernel,
                         cudaFuncAttributeMaxDynamicSharedMemorySize, SMEM_ATTN);

    // fork: W_v GEMM (tensor pipe) runs concurrently with qk GEMM + hash (fma pipe)
    cudaEventRecord(ev_fork, 0);
    cudaStreamWaitEvent(s_aux, ev_fork, 0);
    gemm_tc_kernel<1><<<gt, 256, SMEM_TC, s_aux>>>(queries, W_v, nullptr, nullptr);
    cudaEventRecord(ev_join, s_aux);

    gemm_qk_kernel<<<gq, 256>>>(queries, W_qk);
    hash_sort_kernel<<<BHN * NH, 256>>>(rotations);

    cudaStreamWaitEvent(0, ev_join, 0);   // join before attention

    lsh_attn_kernel<<<BHN * 256, 256, SMEM_ATTN>>>();

    combine_kernel<<<(BHN * T * DH) / 256, 256>>>();

    gemm_tc_kernel<2><<<gt, 256, SMEM_TC>>>(nullptr, W_out, b_out, out);
}